// round 12
// baseline (speedup 1.0000x reference)
#include <cuda_runtime.h>
#include <cuda_bf16.h>

#define BB 8
#define NN 512
#define DD 64

typedef unsigned int u32;
typedef unsigned short u16;

#define SWZ(o)   ((o) ^ (((o) >> 3) & 0x70))   // 128B-row swizzle
#define SCSWZ(o) ((o) ^ (((o) >> 4) & 0x70))   // 256B-row swizzle (scores)

// global scratch: X split into bf16 hi/lo, swizzled tile-ready layout
__device__ __align__(128) char  g_xh[BB * 4 * 16384];   // [b][tile][SWZ(row*128+dp*4)]
__device__ __align__(128) char  g_xl[BB * 4 * 16384];
__device__ float g_hq[BB * NN * 64];     // hq + b1

// ---- dynamic smem offsets (per-CTA), single X buffer ----
#define OXH   0
#define OXL   16384
#define OSCH  32768                      // scores hi [8][256B]
#define OSCL  34816                      // scores lo [8][256B]
#define OPART 36864                      // 2q*128k*2 halves f32 = 2KB
#define OBW   38912                      // interleaved {bias, w2} [2q][64h] f32x2 = 1KB
#define OMBAR 39936                      // 8B mbarrier
#define SMEM_DYN 39952

static __device__ __forceinline__ u32 smem_u32(const void* p) {
    u32 a;
    asm("{ .reg .u64 t; cvta.to.shared.u64 t, %1; cvt.u32.u64 %0, t; }" : "=r"(a) : "l"(p));
    return a;
}
static __device__ __forceinline__ void ldsm_x4(u32* r, u32 addr) {
    asm volatile("ldmatrix.sync.aligned.m8n8.x4.shared.b16 {%0,%1,%2,%3}, [%4];"
        : "=r"(r[0]), "=r"(r[1]), "=r"(r[2]), "=r"(r[3]) : "r"(addr));
}
static __device__ __forceinline__ void ldsm_x4t(u32* r, u32 addr) {
    asm volatile("ldmatrix.sync.aligned.m8n8.x4.trans.shared.b16 {%0,%1,%2,%3}, [%4];"
        : "=r"(r[0]), "=r"(r[1]), "=r"(r[2]), "=r"(r[3]) : "r"(addr));
}
static __device__ __forceinline__ void ldsm_x2(u32* r, u32 addr) {
    asm volatile("ldmatrix.sync.aligned.m8n8.x2.shared.b16 {%0,%1}, [%2];"
        : "=r"(r[0]), "=r"(r[1]) : "r"(addr));
}
static __device__ __forceinline__ void mma_bf16(float* c, const u32* a, const u32* b) {
    asm volatile("mma.sync.aligned.m16n8k16.row.col.f32.bf16.bf16.f32 "
        "{%0,%1,%2,%3}, {%4,%5,%6,%7}, {%8,%9}, {%0,%1,%2,%3};"
        : "+f"(c[0]), "+f"(c[1]), "+f"(c[2]), "+f"(c[3])
        : "r"(a[0]), "r"(a[1]), "r"(a[2]), "r"(a[3]), "r"(b[0]), "r"(b[1]));
}
static __device__ __forceinline__ void split2(float a0, float a1, u32& hp, u32& lp) {
    __nv_bfloat16 h0 = __float2bfloat16(a0), h1 = __float2bfloat16(a1);
    __nv_bfloat16 l0 = __float2bfloat16(a0 - __bfloat162float(h0));
    __nv_bfloat16 l1 = __float2bfloat16(a1 - __bfloat162float(h1));
    hp = (u32)__bfloat16_as_ushort(h0) | ((u32)__bfloat16_as_ushort(h1) << 16);
    lp = (u32)__bfloat16_as_ushort(l0) | ((u32)__bfloat16_as_ushort(l1) << 16);
}
// ---- bulk async copy (sm_90 base ISA) + mbarrier ----
static __device__ __forceinline__ void bulkcp(u32 dst, const void* src, u32 bytes, u32 mbar) {
    asm volatile("{ .reg .u64 g; cvta.to.global.u64 g, %1;\n\t"
        "cp.async.bulk.shared::cluster.global.mbarrier::complete_tx::bytes [%0], [g], %2, [%3]; }"
        :: "r"(dst), "l"(src), "r"(bytes), "r"(mbar) : "memory");
}
static __device__ __forceinline__ void mbar_expect(u32 mbar, u32 bytes) {
    asm volatile("mbarrier.arrive.expect_tx.shared.b64 _, [%0], %1;"
        :: "r"(mbar), "r"(bytes) : "memory");
}
#define MBAR_INIT(a, n) asm volatile("mbarrier.init.shared.b64 [%0], %1;" :: "r"(a), "r"(n) : "memory")
#define MBAR_WAIT(addr, ph) do { u32 _done; \
    asm volatile("{ .reg .pred p; mbarrier.try_wait.parity.acquire.cta.shared::cta.b64 p, [%1], %2; selp.b32 %0,1,0,p; }" \
        : "=r"(_done) : "r"(addr), "r"(ph) : "memory"); \
    while (!_done) { \
        asm volatile("{ .reg .pred p; mbarrier.try_wait.parity.acquire.cta.shared::cta.b64 p, [%1], %2, 0x989680; selp.b32 %0,1,0,p; }" \
            : "=r"(_done) : "r"(addr), "r"(ph) : "memory"); } } while (0)

// ---------------------------------------------------------------------------
// Fused prep: (a) split X rows into bf16 hi/lo swizzled tiles,
//             (b) hq[b,n,h] = x . (Wq+Wd)[h,:] + b1[h].
// Grid 512 = 8b x 64 slices of 8 rows; 128 threads.
// ---------------------------------------------------------------------------
__global__ __launch_bounds__(128) void prep(
    const float* __restrict__ X, const float* __restrict__ W1,
    const float* __restrict__ B1)
{
    __shared__ float sx[8 * DD];
    const int tid = threadIdx.x, b = blockIdx.x >> 6, n0 = (blockIdx.x & 63) * 8;
    reinterpret_cast<float4*>(sx)[tid] =
        reinterpret_cast<const float4*>(X + (b * NN + n0) * DD)[tid];
    __syncthreads();

    {   // xsplit part: 8 rows x 32 dp
        const int t = n0 >> 7, rbase = n0 & 127;
        char* dh = g_xh + b * 65536 + t * 16384;
        char* dl = g_xl + b * 65536 + t * 16384;
        #pragma unroll
        for (int p = tid; p < 256; p += 128) {
            int r = p >> 5, dp = p & 31;
            float2 v = *(const float2*)(sx + r * DD + dp * 2);
            u32 hp, lp; split2(v.x, v.y, hp, lp);
            u32 o = SWZ((u32)((rbase + r) * 128 + dp * 4));
            *(u32*)(dh + o) = hp;
            *(u32*)(dl + o) = lp;
        }
    }
    {   // hq part: h = tid&63, 4 rows each
        const int h = tid & 63, half = tid >> 6;
        const float bb = __ldg(B1 + h);
        const float4* w1row = reinterpret_cast<const float4*>(W1 + h * 256);
        float4 w[16];
        #pragma unroll
        for (int j = 0; j < 16; j++) {
            float4 wq = __ldg(&w1row[j]);
            float4 wd = __ldg(&w1row[32 + j]);
            w[j] = make_float4(wq.x + wd.x, wq.y + wd.y, wq.z + wd.z, wq.w + wd.w);
        }
        #pragma unroll
        for (int nn = half * 4; nn < half * 4 + 4; nn++) {
            const float4* xr = reinterpret_cast<const float4*>(sx + nn * DD);
            float s = 0.f;
            #pragma unroll
            for (int j = 0; j < 16; j++) {
                float4 xv = xr[j];
                s += w[j].x * xv.x + w[j].y * xv.y + w[j].z * xv.z + w[j].w * xv.w;
            }
            g_hq[(b * NN + n0 + nn) * 64 + h] = s + bb;
        }
    }
}

// ---------------------------------------------------------------------------
// Main. One CTA = (b, queries qb, qb+1). 4 warps = 2 q x 2 h-halves.
// Single X buffer, 4 CTAs/SM; A' mma B-frags in registers; X tiles staged
// via cp.async.bulk + mbarrier. Swizzled addresses hoisted out of hot loops.
// ---------------------------------------------------------------------------
__global__ __launch_bounds__(128, 4) void din_mma(
    const float* __restrict__ X, const float* __restrict__ VM,
    const float* __restrict__ W1, const float* __restrict__ PA,
    const float* __restrict__ W2, const float* __restrict__ B2,
    float* __restrict__ OUT)
{
    extern __shared__ __align__(128) char sm[];
    const u32 smb = smem_u32(sm);
    const u32 mbar = smb + OMBAR;

    const int tid = threadIdx.x, wid = tid >> 5, lid = tid & 31;
    const int q_w = wid >> 1, hh = wid & 1;
    const int b = blockIdx.x & 7, g = blockIdx.x >> 3;      // g 0..255
    const int qb = 2 * (255 - g);              // long queries first
    const int q_mine = qb + q_w;
    const int nt = ((qb + 1) >> 7) + 1;
    const float* Xb = X + b * NN * DD;
    float* part = (float*)(sm + OPART);

    // zero score buffers (rows 2-7 stay zero forever; row 4 is the
    // guaranteed-zero source for the encoded-phase x4 loads)
    for (int p = tid; p < 1024; p += 128) ((u32*)(sm + OSCH))[p] = 0;
    // interleaved {bias = hq+b1, w2} per (q, h)
    ((float2*)(sm + OBW))[tid] = make_float2(
        g_hq[(b * NN + qb + (tid >> 6)) * 64 + (tid & 63)],
        __ldg(W2 + (tid & 63)));
    if (tid == 0) MBAR_INIT(mbar, 1);

    // ---- A' staging (128 rows = 2q x 64h) into X buffer, frags -> regs ----
    u32 bh[4][4][2], bl[4][4][2];
    for (int p = tid; p < 4096; p += 128) {
        int r = p >> 5, dp = p & 31, d = dp * 2;
        int q = qb + (r >> 6);
        const float* w1r = W1 + (r & 63) * 256;
        float x0 = __ldg(Xb + q * DD + d), x1 = __ldg(Xb + q * DD + d + 1);
        float a0 = fmaf(__ldg(w1r + 192 + d),     x0, __ldg(w1r + 64 + d)     - __ldg(w1r + 128 + d));
        float a1 = fmaf(__ldg(w1r + 192 + d + 1), x1, __ldg(w1r + 64 + d + 1) - __ldg(w1r + 128 + d + 1));
        u32 hp, lp; split2(a0, a1, hp, lp);
        u32 o = SWZ((u32)(r * 128 + dp * 4));
        *(u32*)(sm + OXH + o) = hp;
        *(u32*)(sm + OXL + o) = lp;
    }
    __syncthreads();
    {
        int rbase = q_w * 64 + hh * 32;
        #pragma unroll
        for (int nb = 0; nb < 4; nb++)
            #pragma unroll
            for (int ks = 0; ks < 4; ks++) {
                u32 o = SWZ((u32)((rbase + nb * 8 + (lid & 7)) * 128
                                  + ks * 32 + ((lid >> 3) & 1) * 16));
                ldsm_x2(bh[nb][ks], smb + OXH + o);
                ldsm_x2(bl[nb][ks], smb + OXL + o);
            }
    }
    __syncthreads();   // frags loaded; buffer free, mbarrier init visible

    // ---- prefetch tile 0 (bulk) ----
    if (tid == 0) {
        mbar_expect(mbar, 32768);
        bulkcp(smb + OXH, g_xh + b * 65536, 16384, mbar);
        bulkcp(smb + OXL, g_xl + b * 65536, 16384, mbar);
    }

    // ---- hoisted swizzled bases (mi/kt strides are 2048 = swizzle-neutral) ----
    u32 aoff[4];   // S-phase A-frag ldsm offsets, + mi*2048
    {
        int r15 = lid & 15, acolb = (lid >> 4) * 16;
        #pragma unroll
        for (int ks = 0; ks < 4; ks++)
            aoff[ks] = SWZ((u32)(r15 * 128 + ks * 32 + acolb));
    }
    const u32 xob = SWZ((u32)((lid & 15) * 128 + wid * 32 + (lid >> 4) * 16));
    const int r8 = lid & 7, grp = lid >> 3;
    const u32 sobase = (u32)(r8 * 256 + (grp >> 1) * 16);
    const u32 som = (u32)(r8 * 16);        // SCSWZ xor mask (depends on r8 only)

    const float aslope = __ldg(PA);
    const float b2v    = __ldg(B2);
    float ec0[4] = {0.f, 0.f, 0.f, 0.f};
    float ec1[4] = {0.f, 0.f, 0.f, 0.f};

    #pragma unroll 1
    for (int t = 0; t < nt; t++) {
        const int k0 = t << 7;
        const u32 xh_b = smb + OXH, xl_b = smb + OXL;
        MBAR_WAIT(mbar, t & 1);    // tile data ready (acquire)

        // ========== S phase: warp = (q_w, 32 h of half hh) ==========
        const int mi_hi = (k0 <= q_mine) ? min(8, ((q_mine - k0) >> 4) + 1) : 0;
        #pragma unroll 1
        for (int mi = 0; mi < mi_hi; mi++) {
            const u32 moff = (u32)(mi * 2048);
            u32 ah[4][4], al[4][4];
            #pragma unroll
            for (int ks = 0; ks < 4; ks++) {
                ldsm_x4(ah[ks], xh_b + aoff[ks] + moff);
                ldsm_x4(al[ks], xl_b + aoff[ks] + moff);
            }
            float c[4][4];
            #pragma unroll
            for (int nb = 0; nb < 4; nb++)
                #pragma unroll
                for (int i = 0; i < 4; i++) c[nb][i] = 0.f;
            #pragma unroll
            for (int nb = 0; nb < 4; nb++)
                #pragma unroll
                for (int ks = 0; ks < 4; ks++) {
                    mma_bf16(c[nb], ah[ks], bh[nb][ks]);
                    mma_bf16(c[nb], ah[ks], bl[nb][ks]);
                    mma_bf16(c[nb], al[ks], bh[nb][ks]);
                }
            float s0 = 0.f, s8 = 0.f;
            #pragma unroll
            for (int nb = 0; nb < 4; nb++) {
                int hcol = hh * 32 + nb * 8 + 2 * (lid & 3);
                float4 bw = *(const float4*)(sm + OBW + (q_w * 64 + hcol) * 8);
                // bw = {bias_h, w2_h, bias_h1, w2_h1}
                float v0 = c[nb][0] + bw.x, v1 = c[nb][1] + bw.z;
                float v2 = c[nb][2] + bw.x, v3 = c[nb][3] + bw.z;
                float p0 = fmaf(aslope, fminf(v0, 0.f), fmaxf(v0, 0.f));
                float p1 = fmaf(aslope, fminf(v1, 0.f), fmaxf(v1, 0.f));
                float p2 = fmaf(aslope, fminf(v2, 0.f), fmaxf(v2, 0.f));
                float p3 = fmaf(aslope, fminf(v3, 0.f), fmaxf(v3, 0.f));
                s0 = fmaf(p0, bw.y, fmaf(p1, bw.w, s0));
                s8 = fmaf(p2, bw.y, fmaf(p3, bw.w, s8));
            }
            s0 += __shfl_xor_sync(0xffffffffu, s0, 1);
            s0 += __shfl_xor_sync(0xffffffffu, s0, 2);
            s8 += __shfl_xor_sync(0xffffffffu, s8, 1);
            s8 += __shfl_xor_sync(0xffffffffu, s8, 2);
            if ((lid & 3) == 0) {
                int kr = mi * 16 + (lid >> 2);
                part[(q_w * 128 + kr) * 2 + hh]     = s0;
                part[(q_w * 128 + kr + 8) * 2 + hh] = s8;
            }
        }
        for (int mi = mi_hi; mi < 8; mi++)
            if (lid < 16) part[(q_w * 128 + mi * 16 + lid) * 2 + hh] = 0.f;
        __syncthreads();

        // ---- combine h-halves -> masked scores (key-pair per thread) ----
        {
            int q = tid >> 6, kp = tid & 63;
            float4 pv = *(const float4*)(part + (q * 128 + 2 * kp) * 2);
            float2 vm = __ldg((const float2*)(VM + b * NN + k0 + 2 * kp));
            int kg = k0 + 2 * kp, qq = qb + q;
            float cm0 = (kg     <= qq) ? vm.x : 0.f;
            float cm1 = (kg + 1 <= qq) ? vm.y : 0.f;
            float s0 = (pv.x + pv.y + b2v) * cm0;
            float s1 = (pv.z + pv.w + b2v) * cm1;
            u32 hp, lp; split2(s0, s1, hp, lp);
            u32 o = SCSWZ((u32)(q * 256 + kp * 4));
            *(u32*)(sm + OSCH + o) = hp;
            *(u32*)(sm + OSCL + o) = lp;
        }
        __syncthreads();

        // ========== encoded mma: ec += scores . X (causally bounded) ========
        {
            const int kt_hi = min(8, ((qb + 1 - k0) >> 4) + 1);
            #pragma unroll 1
            for (int kt = 0; kt < kt_hi; kt++) {
                // scores A-frag: one x4 each (zero rows sourced from row 4)
                u32 off = (grp & 1) ? 1088u : ((sobase + (u32)(kt * 32)) ^ som);
                u32 ash[4], asl[4];
                ldsm_x4(ash, smb + OSCH + off);
                ldsm_x4(asl, smb + OSCL + off);
                // X B-frags: one x4t each for hi/lo (16 d-cols per warp)
                u32 xo = xob + (u32)(kt * 2048);
                u32 bxh[4], bxl[4];
                ldsm_x4t(bxh, xh_b + xo);
                ldsm_x4t(bxl, xl_b + xo);
                mma_bf16(ec0, ash, &bxh[0]);
                mma_bf16(ec0, ash, &bxl[0]);
                mma_bf16(ec0, asl, &bxh[0]);
                mma_bf16(ec1, ash, &bxh[2]);
                mma_bf16(ec1, ash, &bxl[2]);
                mma_bf16(ec1, asl, &bxh[2]);
            }
        }
        __syncthreads();   // buffer free for next tile's prefetch

        if (t + 1 < nt && tid == 0) {
            mbar_expect(mbar, 32768);
            bulkcp(smb + OXH, g_xh + b * 65536 + (t + 1) * 16384, 16384, mbar);
            bulkcp(smb + OXL, g_xl + b * 65536 + (t + 1) * 16384, 16384, mbar);
        }
    }

    // ---- output: rows 0-1 of ec0/ec1 (lanes 0-7) ----
    if (lid < 8) {
        int q = lid >> 2, d0 = wid * 16 + 2 * (lid & 3);
        *(float2*)(OUT + (b * NN + qb + q) * DD + d0)     = make_float2(ec0[0], ec0[1]);
        *(float2*)(OUT + (b * NN + qb + q) * DD + d0 + 8) = make_float2(ec1[0], ec1[1]);
    }
}

// ---------------------------------------------------------------------------
// Inputs (metadata order):
//  0 past_lengths (unused)  1 user_embeddings [8,512,64] f32  2 valid_mask [8,512]
//  3 W1 [64,256]  4 b1 [64]  5 prelu_a [1]  6 W2 [1,64]  7 b2 [1]
// Output: encoded [8,512,64] f32
// ---------------------------------------------------------------------------
extern "C" void kernel_launch(void* const* d_in, const int* in_sizes, int n_in,
                              void* d_out, int out_size)
{
    const float* X  = (const float*)d_in[1];
    const float* VM = (const float*)d_in[2];
    const float* W1 = (const float*)d_in[3];
    const float* b1 = (const float*)d_in[4];
    const float* pa = (const float*)d_in[5];
    const float* W2 = (const float*)d_in[6];
    const float* b2 = (const float*)d_in[7];
    float* OUT = (float*)d_out;

    cudaFuncSetAttribute(din_mma, cudaFuncAttributeMaxDynamicSharedMemorySize, SMEM_DYN);
    prep<<<512, 128>>>(X, W1, b1);
    din_mma<<<BB * NN / 2, 128, SMEM_DYN>>>(X, VM, W1, pa, W2, b2, OUT);
}

// round 13
// speedup vs baseline: 1.0547x; 1.0547x over previous
#include <cuda_runtime.h>
#include <cuda_bf16.h>

#define BB 8
#define NN 512
#define DD 64

typedef unsigned int u32;
typedef unsigned short u16;

#define SWZ(o)   ((o) ^ (((o) >> 3) & 0x70))   // 128B-row swizzle
#define SCSWZ(o) ((o) ^ (((o) >> 4) & 0x70))   // 256B-row swizzle (scores)

// global scratch: X split into bf16 hi/lo, swizzled tile-ready layout
__device__ __align__(128) char  g_xh[BB * 4 * 16384];   // [b][tile][SWZ(row*128+dp*4)]
__device__ __align__(128) char  g_xl[BB * 4 * 16384];
__device__ float g_hq[BB * NN * 64];     // hq + b1

// ---- dynamic smem offsets (per-CTA), single X buffer ----
#define OXH   0
#define OXL   16384
#define OSCH  32768                      // scores hi [8][256B]
#define OSCL  34816                      // scores lo [8][256B]
#define OPART 36864                      // 2q*128k*2 halves f32 = 2KB
#define OBW   38912                      // interleaved {bias, w2} [2q][64h] f32x2 = 1KB
#define OMBAR 39936                      // 8B mbarrier
#define SMEM_DYN 39952

static __device__ __forceinline__ u32 smem_u32(const void* p) {
    u32 a;
    asm("{ .reg .u64 t; cvta.to.shared.u64 t, %1; cvt.u32.u64 %0, t; }" : "=r"(a) : "l"(p));
    return a;
}
static __device__ __forceinline__ void ldsm_x4(u32* r, u32 addr) {
    asm volatile("ldmatrix.sync.aligned.m8n8.x4.shared.b16 {%0,%1,%2,%3}, [%4];"
        : "=r"(r[0]), "=r"(r[1]), "=r"(r[2]), "=r"(r[3]) : "r"(addr));
}
static __device__ __forceinline__ void ldsm_x4t(u32* r, u32 addr) {
    asm volatile("ldmatrix.sync.aligned.m8n8.x4.trans.shared.b16 {%0,%1,%2,%3}, [%4];"
        : "=r"(r[0]), "=r"(r[1]), "=r"(r[2]), "=r"(r[3]) : "r"(addr));
}
static __device__ __forceinline__ void ldsm_x2(u32* r, u32 addr) {
    asm volatile("ldmatrix.sync.aligned.m8n8.x2.shared.b16 {%0,%1}, [%2];"
        : "=r"(r[0]), "=r"(r[1]) : "r"(addr));
}
static __device__ __forceinline__ void mma_bf16(float* c, const u32* a, const u32* b) {
    asm volatile("mma.sync.aligned.m16n8k16.row.col.f32.bf16.bf16.f32 "
        "{%0,%1,%2,%3}, {%4,%5,%6,%7}, {%8,%9}, {%0,%1,%2,%3};"
        : "+f"(c[0]), "+f"(c[1]), "+f"(c[2]), "+f"(c[3])
        : "r"(a[0]), "r"(a[1]), "r"(a[2]), "r"(a[3]), "r"(b[0]), "r"(b[1]));
}
static __device__ __forceinline__ void split2(float a0, float a1, u32& hp, u32& lp) {
    __nv_bfloat16 h0 = __float2bfloat16(a0), h1 = __float2bfloat16(a1);
    __nv_bfloat16 l0 = __float2bfloat16(a0 - __bfloat162float(h0));
    __nv_bfloat16 l1 = __float2bfloat16(a1 - __bfloat162float(h1));
    hp = (u32)__bfloat16_as_ushort(h0) | ((u32)__bfloat16_as_ushort(h1) << 16);
    lp = (u32)__bfloat16_as_ushort(l0) | ((u32)__bfloat16_as_ushort(l1) << 16);
}
// ---- bulk async copy (sm_90 base ISA) + mbarrier ----
static __device__ __forceinline__ void bulkcp(u32 dst, const void* src, u32 bytes, u32 mbar) {
    asm volatile("{ .reg .u64 g; cvta.to.global.u64 g, %1;\n\t"
        "cp.async.bulk.shared::cluster.global.mbarrier::complete_tx::bytes [%0], [g], %2, [%3]; }"
        :: "r"(dst), "l"(src), "r"(bytes), "r"(mbar) : "memory");
}
static __device__ __forceinline__ void mbar_expect(u32 mbar, u32 bytes) {
    asm volatile("mbarrier.arrive.expect_tx.shared.b64 _, [%0], %1;"
        :: "r"(mbar), "r"(bytes) : "memory");
}
#define MBAR_INIT(a, n) asm volatile("mbarrier.init.shared.b64 [%0], %1;" :: "r"(a), "r"(n) : "memory")
#define MBAR_WAIT(addr, ph) do { u32 _done; \
    asm volatile("{ .reg .pred p; mbarrier.try_wait.parity.acquire.cta.shared::cta.b64 p, [%1], %2; selp.b32 %0,1,0,p; }" \
        : "=r"(_done) : "r"(addr), "r"(ph) : "memory"); \
    while (!_done) { \
        asm volatile("{ .reg .pred p; mbarrier.try_wait.parity.acquire.cta.shared::cta.b64 p, [%1], %2, 0x989680; selp.b32 %0,1,0,p; }" \
            : "=r"(_done) : "r"(addr), "r"(ph) : "memory"); } } while (0)

// ---------------------------------------------------------------------------
// Fused prep (R11 shape): (a) split X rows into bf16 hi/lo swizzled tiles,
//                         (b) hq[b,n,h] = x . (Wq+Wd)[h,:] + b1[h].
// Grid 256 = 8b x 32 slices of 16 rows; 128 threads.
// ---------------------------------------------------------------------------
__global__ __launch_bounds__(128) void prep(
    const float* __restrict__ X, const float* __restrict__ W1,
    const float* __restrict__ B1)
{
    __shared__ float sx[16 * DD];
    const int tid = threadIdx.x, b = blockIdx.x >> 5, n0 = (blockIdx.x & 31) * 16;
    for (int i = tid; i < 256; i += 128)
        reinterpret_cast<float4*>(sx)[i] =
            reinterpret_cast<const float4*>(X + (b * NN + n0) * DD)[i];
    __syncthreads();

    {   // xsplit part
        const int t = n0 >> 7, rbase = n0 & 127;
        char* dh = g_xh + b * 65536 + t * 16384;
        char* dl = g_xl + b * 65536 + t * 16384;
        #pragma unroll 4
        for (int p = tid; p < 512; p += 128) {
            int r = p >> 5, dp = p & 31;
            float2 v = *(const float2*)(sx + r * DD + dp * 2);
            u32 hp, lp; split2(v.x, v.y, hp, lp);
            u32 o = SWZ((u32)((rbase + r) * 128 + dp * 4));
            *(u32*)(dh + o) = hp;
            *(u32*)(dl + o) = lp;
        }
    }
    if (tid < 64) {   // hq part, thread = h
        const float bb = __ldg(B1 + tid);
        const float4* w1row = reinterpret_cast<const float4*>(W1 + tid * 256);
        float4 w[16];
        #pragma unroll
        for (int j = 0; j < 16; j++) {
            float4 wq = __ldg(&w1row[j]);
            float4 wd = __ldg(&w1row[32 + j]);
            w[j] = make_float4(wq.x + wd.x, wq.y + wd.y, wq.z + wd.z, wq.w + wd.w);
        }
        for (int nn = 0; nn < 16; nn++) {
            const float4* xr = reinterpret_cast<const float4*>(sx + nn * DD);
            float s = 0.f;
            #pragma unroll
            for (int j = 0; j < 16; j++) {
                float4 xv = xr[j];
                s += w[j].x * xv.x + w[j].y * xv.y + w[j].z * xv.z + w[j].w * xv.w;
            }
            g_hq[(b * NN + n0 + nn) * 64 + tid] = s + bb;
        }
    }
}

// ---------------------------------------------------------------------------
// Main (R12, best measured). One CTA = (b, queries qb, qb+1).
// 4 warps = 2 q x 2 h-halves, single X buffer, 4 CTAs/SM, A' frags in regs,
// X tiles staged via cp.async.bulk + mbarrier, hoisted swizzled addresses.
// ---------------------------------------------------------------------------
__global__ __launch_bounds__(128, 4) void din_mma(
    const float* __restrict__ X, const float* __restrict__ VM,
    const float* __restrict__ W1, const float* __restrict__ PA,
    const float* __restrict__ W2, const float* __restrict__ B2,
    float* __restrict__ OUT)
{
    extern __shared__ __align__(128) char sm[];
    const u32 smb = smem_u32(sm);
    const u32 mbar = smb + OMBAR;

    const int tid = threadIdx.x, wid = tid >> 5, lid = tid & 31;
    const int q_w = wid >> 1, hh = wid & 1;
    const int b = blockIdx.x & 7, g = blockIdx.x >> 3;      // g 0..255
    const int qb = 2 * (255 - g);              // long queries first
    const int q_mine = qb + q_w;
    const int nt = ((qb + 1) >> 7) + 1;
    const float* Xb = X + b * NN * DD;
    float* part = (float*)(sm + OPART);

    // zero score buffers (rows 2-7 stay zero forever; row 4 is the
    // guaranteed-zero source for the encoded-phase x4 loads)
    for (int p = tid; p < 1024; p += 128) ((u32*)(sm + OSCH))[p] = 0;
    // interleaved {bias = hq+b1, w2} per (q, h)
    ((float2*)(sm + OBW))[tid] = make_float2(
        g_hq[(b * NN + qb + (tid >> 6)) * 64 + (tid & 63)],
        __ldg(W2 + (tid & 63)));
    if (tid == 0) MBAR_INIT(mbar, 1);

    // ---- A' staging (128 rows = 2q x 64h) into X buffer, frags -> regs ----
    u32 bh[4][4][2], bl[4][4][2];
    for (int p = tid; p < 4096; p += 128) {
        int r = p >> 5, dp = p & 31, d = dp * 2;
        int q = qb + (r >> 6);
        const float* w1r = W1 + (r & 63) * 256;
        float x0 = __ldg(Xb + q * DD + d), x1 = __ldg(Xb + q * DD + d + 1);
        float a0 = fmaf(__ldg(w1r + 192 + d),     x0, __ldg(w1r + 64 + d)     - __ldg(w1r + 128 + d));
        float a1 = fmaf(__ldg(w1r + 192 + d + 1), x1, __ldg(w1r + 64 + d + 1) - __ldg(w1r + 128 + d + 1));
        u32 hp, lp; split2(a0, a1, hp, lp);
        u32 o = SWZ((u32)(r * 128 + dp * 4));
        *(u32*)(sm + OXH + o) = hp;
        *(u32*)(sm + OXL + o) = lp;
    }
    __syncthreads();
    {
        int rbase = q_w * 64 + hh * 32;
        #pragma unroll
        for (int nb = 0; nb < 4; nb++)
            #pragma unroll
            for (int ks = 0; ks < 4; ks++) {
                u32 o = SWZ((u32)((rbase + nb * 8 + (lid & 7)) * 128
                                  + ks * 32 + ((lid >> 3) & 1) * 16));
                ldsm_x2(bh[nb][ks], smb + OXH + o);
                ldsm_x2(bl[nb][ks], smb + OXL + o);
            }
    }
    __syncthreads();   // frags loaded; buffer free, mbarrier init visible

    // ---- prefetch tile 0 (bulk) ----
    if (tid == 0) {
        mbar_expect(mbar, 32768);
        bulkcp(smb + OXH, g_xh + b * 65536, 16384, mbar);
        bulkcp(smb + OXL, g_xl + b * 65536, 16384, mbar);
    }

    // ---- hoisted swizzled bases (mi/kt strides are 2048 = swizzle-neutral) ----
    u32 aoff[4];   // S-phase A-frag ldsm offsets, + mi*2048
    {
        int r15 = lid & 15, acolb = (lid >> 4) * 16;
        #pragma unroll
        for (int ks = 0; ks < 4; ks++)
            aoff[ks] = SWZ((u32)(r15 * 128 + ks * 32 + acolb));
    }
    const u32 xob = SWZ((u32)((lid & 15) * 128 + wid * 32 + (lid >> 4) * 16));
    const int r8 = lid & 7, grp = lid >> 3;
    const u32 sobase = (u32)(r8 * 256 + (grp >> 1) * 16);
    const u32 som = (u32)(r8 * 16);        // SCSWZ xor mask (depends on r8 only)

    const float aslope = __ldg(PA);
    const float b2v    = __ldg(B2);
    float ec0[4] = {0.f, 0.f, 0.f, 0.f};
    float ec1[4] = {0.f, 0.f, 0.f, 0.f};

    #pragma unroll 1
    for (int t = 0; t < nt; t++) {
        const int k0 = t << 7;
        const u32 xh_b = smb + OXH, xl_b = smb + OXL;
        MBAR_WAIT(mbar, t & 1);    // tile data ready (acquire)

        // ========== S phase: warp = (q_w, 32 h of half hh) ==========
        const int mi_hi = (k0 <= q_mine) ? min(8, ((q_mine - k0) >> 4) + 1) : 0;
        #pragma unroll 1
        for (int mi = 0; mi < mi_hi; mi++) {
            const u32 moff = (u32)(mi * 2048);
            u32 ah[4][4], al[4][4];
            #pragma unroll
            for (int ks = 0; ks < 4; ks++) {
                ldsm_x4(ah[ks], xh_b + aoff[ks] + moff);
                ldsm_x4(al[ks], xl_b + aoff[ks] + moff);
            }
            float c[4][4];
            #pragma unroll
            for (int nb = 0; nb < 4; nb++)
                #pragma unroll
                for (int i = 0; i < 4; i++) c[nb][i] = 0.f;
            #pragma unroll
            for (int nb = 0; nb < 4; nb++)
                #pragma unroll
                for (int ks = 0; ks < 4; ks++) {
                    mma_bf16(c[nb], ah[ks], bh[nb][ks]);
                    mma_bf16(c[nb], ah[ks], bl[nb][ks]);
                    mma_bf16(c[nb], al[ks], bh[nb][ks]);
                }
            float s0 = 0.f, s8 = 0.f;
            #pragma unroll
            for (int nb = 0; nb < 4; nb++) {
                int hcol = hh * 32 + nb * 8 + 2 * (lid & 3);
                float4 bw = *(const float4*)(sm + OBW + (q_w * 64 + hcol) * 8);
                // bw = {bias_h, w2_h, bias_h1, w2_h1}
                float v0 = c[nb][0] + bw.x, v1 = c[nb][1] + bw.z;
                float v2 = c[nb][2] + bw.x, v3 = c[nb][3] + bw.z;
                float p0 = fmaf(aslope, fminf(v0, 0.f), fmaxf(v0, 0.f));
                float p1 = fmaf(aslope, fminf(v1, 0.f), fmaxf(v1, 0.f));
                float p2 = fmaf(aslope, fminf(v2, 0.f), fmaxf(v2, 0.f));
                float p3 = fmaf(aslope, fminf(v3, 0.f), fmaxf(v3, 0.f));
                s0 = fmaf(p0, bw.y, fmaf(p1, bw.w, s0));
                s8 = fmaf(p2, bw.y, fmaf(p3, bw.w, s8));
            }
            s0 += __shfl_xor_sync(0xffffffffu, s0, 1);
            s0 += __shfl_xor_sync(0xffffffffu, s0, 2);
            s8 += __shfl_xor_sync(0xffffffffu, s8, 1);
            s8 += __shfl_xor_sync(0xffffffffu, s8, 2);
            if ((lid & 3) == 0) {
                int kr = mi * 16 + (lid >> 2);
                part[(q_w * 128 + kr) * 2 + hh]     = s0;
                part[(q_w * 128 + kr + 8) * 2 + hh] = s8;
            }
        }
        if (mi_hi < 8 && lid < 16) {
            #pragma unroll 1
            for (int mi = mi_hi; mi < 8; mi++)
                part[(q_w * 128 + mi * 16 + lid) * 2 + hh] = 0.f;
        }
        __syncthreads();

        // ---- combine h-halves -> masked scores (key-pair per thread) ----
        {
            int q = tid >> 6, kp = tid & 63;
            float4 pv = *(const float4*)(part + (q * 128 + 2 * kp) * 2);
            float2 vm = __ldg((const float2*)(VM + b * NN + k0 + 2 * kp));
            int kg = k0 + 2 * kp, qq = qb + q;
            float cm0 = (kg     <= qq) ? vm.x : 0.f;
            float cm1 = (kg + 1 <= qq) ? vm.y : 0.f;
            float s0 = (pv.x + pv.y + b2v) * cm0;
            float s1 = (pv.z + pv.w + b2v) * cm1;
            u32 hp, lp; split2(s0, s1, hp, lp);
            u32 o = SCSWZ((u32)(q * 256 + kp * 4));
            *(u32*)(sm + OSCH + o) = hp;
            *(u32*)(sm + OSCL + o) = lp;
        }
        __syncthreads();

        // ========== encoded mma: ec += scores . X (causally bounded) ========
        {
            const int kt_hi = min(8, ((qb + 1 - k0) >> 4) + 1);
            #pragma unroll 1
            for (int kt = 0; kt < kt_hi; kt++) {
                // scores A-frag: one x4 each (zero rows sourced from row 4)
                u32 off = (grp & 1) ? 1088u : ((sobase + (u32)(kt * 32)) ^ som);
                u32 ash[4], asl[4];
                ldsm_x4(ash, smb + OSCH + off);
                ldsm_x4(asl, smb + OSCL + off);
                // X B-frags: one x4t each for hi/lo (16 d-cols per warp)
                u32 xo = xob + (u32)(kt * 2048);
                u32 bxh[4], bxl[4];
                ldsm_x4t(bxh, xh_b + xo);
                ldsm_x4t(bxl, xl_b + xo);
                mma_bf16(ec0, ash, &bxh[0]);
                mma_bf16(ec0, ash, &bxl[0]);
                mma_bf16(ec0, asl, &bxh[0]);
                mma_bf16(ec1, ash, &bxh[2]);
                mma_bf16(ec1, ash, &bxl[2]);
                mma_bf16(ec1, asl, &bxh[2]);
            }
        }
        __syncthreads();   // buffer free for next tile's prefetch

        if (t + 1 < nt && tid == 0) {
            mbar_expect(mbar, 32768);
            bulkcp(smb + OXH, g_xh + b * 65536 + (t + 1) * 16384, 16384, mbar);
            bulkcp(smb + OXL, g_xl + b * 65536 + (t + 1) * 16384, 16384, mbar);
        }
    }

    // ---- output: rows 0-1 of ec0/ec1 (lanes 0-7) ----
    if (lid < 8) {
        int q = lid >> 2, d0 = wid * 16 + 2 * (lid & 3);
        *(float2*)(OUT + (b * NN + qb + q) * DD + d0)     = make_float2(ec0[0], ec0[1]);
        *(float2*)(OUT + (b * NN + qb + q) * DD + d0 + 8) = make_float2(ec1[0], ec1[1]);
    }
}

// ---------------------------------------------------------------------------
// Inputs (metadata order):
//  0 past_lengths (unused)  1 user_embeddings [8,512,64] f32  2 valid_mask [8,512]
//  3 W1 [64,256]  4 b1 [64]  5 prelu_a [1]  6 W2 [1,64]  7 b2 [1]
// Output: encoded [8,512,64] f32
// ---------------------------------------------------------------------------
extern "C" void kernel_launch(void* const* d_in, const int* in_sizes, int n_in,
                              void* d_out, int out_size)
{
    const float* X  = (const float*)d_in[1];
    const float* VM = (const float*)d_in[2];
    const float* W1 = (const float*)d_in[3];
    const float* b1 = (const float*)d_in[4];
    const float* pa = (const float*)d_in[5];
    const float* W2 = (const float*)d_in[6];
    const float* b2 = (const float*)d_in[7];
    float* OUT = (float*)d_out;

    cudaFuncSetAttribute(din_mma, cudaFuncAttributeMaxDynamicSharedMemorySize, SMEM_DYN);
    prep<<<256, 128>>>(X, W1, b1);
    din_mma<<<BB * NN / 2, 128, SMEM_DYN>>>(X, VM, W1, pa, W2, b2, OUT);
}

// round 14
// speedup vs baseline: 1.0603x; 1.0053x over previous
#include <cuda_runtime.h>
#include <cuda_bf16.h>

#define BB 8
#define NN 512
#define DD 64

typedef unsigned int u32;
typedef unsigned short u16;

#define SWZ(o)   ((o) ^ (((o) >> 3) & 0x70))   // 128B-row swizzle
#define SCSWZ(o) ((o) ^ (((o) >> 4) & 0x70))   // 256B-row swizzle (scores)

// global scratch: X split into bf16 hi/lo, swizzled tile-ready layout
__device__ __align__(128) char  g_xh[BB * 4 * 16384];   // [b][tile][SWZ(row*128+dp*4)]
__device__ __align__(128) char  g_xl[BB * 4 * 16384];
__device__ float g_hq[BB * NN * 64];     // hq + b1

// ---- dynamic smem offsets (per-CTA), single X buffer ----
#define OXH   0
#define OXL   16384
#define OSCH  32768                      // scores hi [8][256B]
#define OSCL  34816                      // scores lo [8][256B]
#define OPART 36864                      // 2q*128k*2 halves f32 = 2KB
#define OBW   38912                      // interleaved {bias, w2} [2q][64h] f32x2 = 1KB
#define OMBAR 39936                      // 8B mbarrier
#define SMEM_DYN 39952

static __device__ __forceinline__ u32 smem_u32(const void* p) {
    u32 a;
    asm("{ .reg .u64 t; cvta.to.shared.u64 t, %1; cvt.u32.u64 %0, t; }" : "=r"(a) : "l"(p));
    return a;
}
static __device__ __forceinline__ void ldsm_x4(u32* r, u32 addr) {
    asm volatile("ldmatrix.sync.aligned.m8n8.x4.shared.b16 {%0,%1,%2,%3}, [%4];"
        : "=r"(r[0]), "=r"(r[1]), "=r"(r[2]), "=r"(r[3]) : "r"(addr));
}
static __device__ __forceinline__ void ldsm_x4t(u32* r, u32 addr) {
    asm volatile("ldmatrix.sync.aligned.m8n8.x4.trans.shared.b16 {%0,%1,%2,%3}, [%4];"
        : "=r"(r[0]), "=r"(r[1]), "=r"(r[2]), "=r"(r[3]) : "r"(addr));
}
static __device__ __forceinline__ void ldsm_x2(u32* r, u32 addr) {
    asm volatile("ldmatrix.sync.aligned.m8n8.x2.shared.b16 {%0,%1}, [%2];"
        : "=r"(r[0]), "=r"(r[1]) : "r"(addr));
}
static __device__ __forceinline__ void mma_bf16(float* c, const u32* a, const u32* b) {
    asm volatile("mma.sync.aligned.m16n8k16.row.col.f32.bf16.bf16.f32 "
        "{%0,%1,%2,%3}, {%4,%5,%6,%7}, {%8,%9}, {%0,%1,%2,%3};"
        : "+f"(c[0]), "+f"(c[1]), "+f"(c[2]), "+f"(c[3])
        : "r"(a[0]), "r"(a[1]), "r"(a[2]), "r"(a[3]), "r"(b[0]), "r"(b[1]));
}
static __device__ __forceinline__ void split2(float a0, float a1, u32& hp, u32& lp) {
    __nv_bfloat16 h0 = __float2bfloat16(a0), h1 = __float2bfloat16(a1);
    __nv_bfloat16 l0 = __float2bfloat16(a0 - __bfloat162float(h0));
    __nv_bfloat16 l1 = __float2bfloat16(a1 - __bfloat162float(h1));
    hp = (u32)__bfloat16_as_ushort(h0) | ((u32)__bfloat16_as_ushort(h1) << 16);
    lp = (u32)__bfloat16_as_ushort(l0) | ((u32)__bfloat16_as_ushort(l1) << 16);
}
// ---- bulk async copy (sm_90 base ISA) + mbarrier ----
static __device__ __forceinline__ void bulkcp(u32 dst, const void* src, u32 bytes, u32 mbar) {
    asm volatile("{ .reg .u64 g; cvta.to.global.u64 g, %1;\n\t"
        "cp.async.bulk.shared::cluster.global.mbarrier::complete_tx::bytes [%0], [g], %2, [%3]; }"
        :: "r"(dst), "l"(src), "r"(bytes), "r"(mbar) : "memory");
}
static __device__ __forceinline__ void mbar_expect(u32 mbar, u32 bytes) {
    asm volatile("mbarrier.arrive.expect_tx.shared.b64 _, [%0], %1;"
        :: "r"(mbar), "r"(bytes) : "memory");
}
#define MBAR_INIT(a, n) asm volatile("mbarrier.init.shared.b64 [%0], %1;" :: "r"(a), "r"(n) : "memory")
#define MBAR_WAIT(addr, ph) do { u32 _done; \
    asm volatile("{ .reg .pred p; mbarrier.try_wait.parity.acquire.cta.shared::cta.b64 p, [%1], %2; selp.b32 %0,1,0,p; }" \
        : "=r"(_done) : "r"(addr), "r"(ph) : "memory"); \
    while (!_done) { \
        asm volatile("{ .reg .pred p; mbarrier.try_wait.parity.acquire.cta.shared::cta.b64 p, [%1], %2, 0x989680; selp.b32 %0,1,0,p; }" \
            : "=r"(_done) : "r"(addr), "r"(ph) : "memory"); } } while (0)

// ---------------------------------------------------------------------------
// Fused prep (R11 shape): (a) split X rows into bf16 hi/lo swizzled tiles,
//                         (b) hq[b,n,h] = x . (Wq+Wd)[h,:] + b1[h].
// Grid 256 = 8b x 32 slices of 16 rows; 128 threads.
// ---------------------------------------------------------------------------
__global__ __launch_bounds__(128) void prep(
    const float* __restrict__ X, const float* __restrict__ W1,
    const float* __restrict__ B1)
{
    __shared__ float sx[16 * DD];
    const int tid = threadIdx.x, b = blockIdx.x >> 5, n0 = (blockIdx.x & 31) * 16;
    for (int i = tid; i < 256; i += 128)
        reinterpret_cast<float4*>(sx)[i] =
            reinterpret_cast<const float4*>(X + (b * NN + n0) * DD)[i];
    __syncthreads();

    {   // xsplit part
        const int t = n0 >> 7, rbase = n0 & 127;
        char* dh = g_xh + b * 65536 + t * 16384;
        char* dl = g_xl + b * 65536 + t * 16384;
        #pragma unroll 4
        for (int p = tid; p < 512; p += 128) {
            int r = p >> 5, dp = p & 31;
            float2 v = *(const float2*)(sx + r * DD + dp * 2);
            u32 hp, lp; split2(v.x, v.y, hp, lp);
            u32 o = SWZ((u32)((rbase + r) * 128 + dp * 4));
            *(u32*)(dh + o) = hp;
            *(u32*)(dl + o) = lp;
        }
    }
    if (tid < 64) {   // hq part, thread = h
        const float bb = __ldg(B1 + tid);
        const float4* w1row = reinterpret_cast<const float4*>(W1 + tid * 256);
        float4 w[16];
        #pragma unroll
        for (int j = 0; j < 16; j++) {
            float4 wq = __ldg(&w1row[j]);
            float4 wd = __ldg(&w1row[32 + j]);
            w[j] = make_float4(wq.x + wd.x, wq.y + wd.y, wq.z + wd.z, wq.w + wd.w);
        }
        for (int nn = 0; nn < 16; nn++) {
            const float4* xr = reinterpret_cast<const float4*>(sx + nn * DD);
            float s = 0.f;
            #pragma unroll
            for (int j = 0; j < 16; j++) {
                float4 xv = xr[j];
                s += w[j].x * xv.x + w[j].y * xv.y + w[j].z * xv.z + w[j].w * xv.w;
            }
            g_hq[(b * NN + n0 + nn) * 64 + tid] = s + bb;
        }
    }
}

// ---------------------------------------------------------------------------
// Main. One CTA = (b, queries qb, qb+1). 4 warps = 2 q x 2 h-halves.
// Single X buffer, 4 CTAs/SM, A' frags in regs, cp.async.bulk staging.
// Encoded phase computes encoded^T = X^T . scores^T (X dense as A operand,
// scores' 2 valid rows in the cheap N direction): 3 mma/kt/warp (was 6).
// ---------------------------------------------------------------------------
__global__ __launch_bounds__(128, 4) void din_mma(
    const float* __restrict__ X, const float* __restrict__ VM,
    const float* __restrict__ W1, const float* __restrict__ PA,
    const float* __restrict__ W2, const float* __restrict__ B2,
    float* __restrict__ OUT)
{
    extern __shared__ __align__(128) char sm[];
    const u32 smb = smem_u32(sm);
    const u32 mbar = smb + OMBAR;

    const int tid = threadIdx.x, wid = tid >> 5, lid = tid & 31;
    const int q_w = wid >> 1, hh = wid & 1;
    const int b = blockIdx.x & 7, g = blockIdx.x >> 3;      // g 0..255
    const int qb = 2 * (255 - g);              // long queries first
    const int q_mine = qb + q_w;
    const int nt = ((qb + 1) >> 7) + 1;
    const float* Xb = X + b * NN * DD;
    float* part = (float*)(sm + OPART);

    // zero score buffers (rows 2-7 stay zero forever; they feed the zero
    // N-columns of the encoded-phase B operand)
    for (int p = tid; p < 1024; p += 128) ((u32*)(sm + OSCH))[p] = 0;
    // interleaved {bias = hq+b1, w2} per (q, h)
    ((float2*)(sm + OBW))[tid] = make_float2(
        g_hq[(b * NN + qb + (tid >> 6)) * 64 + (tid & 63)],
        __ldg(W2 + (tid & 63)));
    if (tid == 0) MBAR_INIT(mbar, 1);

    // ---- A' staging (128 rows = 2q x 64h) into X buffer, frags -> regs ----
    u32 bh[4][4][2], bl[4][4][2];
    for (int p = tid; p < 4096; p += 128) {
        int r = p >> 5, dp = p & 31, d = dp * 2;
        int q = qb + (r >> 6);
        const float* w1r = W1 + (r & 63) * 256;
        float x0 = __ldg(Xb + q * DD + d), x1 = __ldg(Xb + q * DD + d + 1);
        float a0 = fmaf(__ldg(w1r + 192 + d),     x0, __ldg(w1r + 64 + d)     - __ldg(w1r + 128 + d));
        float a1 = fmaf(__ldg(w1r + 192 + d + 1), x1, __ldg(w1r + 64 + d + 1) - __ldg(w1r + 128 + d + 1));
        u32 hp, lp; split2(a0, a1, hp, lp);
        u32 o = SWZ((u32)(r * 128 + dp * 4));
        *(u32*)(sm + OXH + o) = hp;
        *(u32*)(sm + OXL + o) = lp;
    }
    __syncthreads();
    {
        int rbase = q_w * 64 + hh * 32;
        #pragma unroll
        for (int nb = 0; nb < 4; nb++)
            #pragma unroll
            for (int ks = 0; ks < 4; ks++) {
                u32 o = SWZ((u32)((rbase + nb * 8 + (lid & 7)) * 128
                                  + ks * 32 + ((lid >> 3) & 1) * 16));
                ldsm_x2(bh[nb][ks], smb + OXH + o);
                ldsm_x2(bl[nb][ks], smb + OXL + o);
            }
    }
    __syncthreads();   // frags loaded; buffer free, mbarrier init visible

    // ---- prefetch tile 0 (bulk) ----
    if (tid == 0) {
        mbar_expect(mbar, 32768);
        bulkcp(smb + OXH, g_xh + b * 65536, 16384, mbar);
        bulkcp(smb + OXL, g_xl + b * 65536, 16384, mbar);
    }

    // ---- hoisted swizzled bases ----
    u32 aoff[4];   // S-phase A-frag ldsm offsets, + mi*2048
    {
        int r15 = lid & 15, acolb = (lid >> 4) * 16;
        #pragma unroll
        for (int ks = 0; ks < 4; ks++)
            aoff[ks] = SWZ((u32)(r15 * 128 + ks * 32 + acolb));
    }
    // encoded X A-frag (x4t): row = (lid&7) + bit4(lid)*8, colbyte = wid*32 + bit3(lid)*16
    const u32 xab = SWZ((u32)(((lid & 7) + ((lid >> 4) & 1) * 8) * 128
                              + wid * 32 + ((lid >> 3) & 1) * 16));
    // encoded scores B-frag (x2, lanes 0-15): row = lid&7, seg = bit3
    const u32 sb_raw  = (u32)((lid & 7) * 256 + ((lid >> 3) & 1) * 16);
    const u32 sb_mask = (u32)((lid & 7) * 16);   // SCSWZ xor (kt*32 stays in bits 5-7)

    const float aslope = __ldg(PA);
    const float b2v    = __ldg(B2);
    float ec[4] = {0.f, 0.f, 0.f, 0.f};   // encoded^T c-frag: d rows, q cols

    #pragma unroll 1
    for (int t = 0; t < nt; t++) {
        const int k0 = t << 7;
        const u32 xh_b = smb + OXH, xl_b = smb + OXL;
        MBAR_WAIT(mbar, t & 1);    // tile data ready (acquire)

        // ========== S phase: warp = (q_w, 32 h of half hh) ==========
        const int mi_hi = (k0 <= q_mine) ? min(8, ((q_mine - k0) >> 4) + 1) : 0;
        #pragma unroll 1
        for (int mi = 0; mi < mi_hi; mi++) {
            const u32 moff = (u32)(mi * 2048);
            u32 ah[4][4], al[4][4];
            #pragma unroll
            for (int ks = 0; ks < 4; ks++) {
                ldsm_x4(ah[ks], xh_b + aoff[ks] + moff);
                ldsm_x4(al[ks], xl_b + aoff[ks] + moff);
            }
            float c[4][4];
            #pragma unroll
            for (int nb = 0; nb < 4; nb++)
                #pragma unroll
                for (int i = 0; i < 4; i++) c[nb][i] = 0.f;
            #pragma unroll
            for (int nb = 0; nb < 4; nb++)
                #pragma unroll
                for (int ks = 0; ks < 4; ks++) {
                    mma_bf16(c[nb], ah[ks], bh[nb][ks]);
                    mma_bf16(c[nb], ah[ks], bl[nb][ks]);
                    mma_bf16(c[nb], al[ks], bh[nb][ks]);
                }
            float s0 = 0.f, s8 = 0.f;
            #pragma unroll
            for (int nb = 0; nb < 4; nb++) {
                int hcol = hh * 32 + nb * 8 + 2 * (lid & 3);
                float4 bw = *(const float4*)(sm + OBW + (q_w * 64 + hcol) * 8);
                float v0 = c[nb][0] + bw.x, v1 = c[nb][1] + bw.z;
                float v2 = c[nb][2] + bw.x, v3 = c[nb][3] + bw.z;
                float p0 = fmaf(aslope, fminf(v0, 0.f), fmaxf(v0, 0.f));
                float p1 = fmaf(aslope, fminf(v1, 0.f), fmaxf(v1, 0.f));
                float p2 = fmaf(aslope, fminf(v2, 0.f), fmaxf(v2, 0.f));
                float p3 = fmaf(aslope, fminf(v3, 0.f), fmaxf(v3, 0.f));
                s0 = fmaf(p0, bw.y, fmaf(p1, bw.w, s0));
                s8 = fmaf(p2, bw.y, fmaf(p3, bw.w, s8));
            }
            s0 += __shfl_xor_sync(0xffffffffu, s0, 1);
            s0 += __shfl_xor_sync(0xffffffffu, s0, 2);
            s8 += __shfl_xor_sync(0xffffffffu, s8, 1);
            s8 += __shfl_xor_sync(0xffffffffu, s8, 2);
            if ((lid & 3) == 0) {
                int kr = mi * 16 + (lid >> 2);
                part[(q_w * 128 + kr) * 2 + hh]     = s0;
                part[(q_w * 128 + kr + 8) * 2 + hh] = s8;
            }
        }
        if (mi_hi < 8 && lid < 16) {
            #pragma unroll 1
            for (int mi = mi_hi; mi < 8; mi++)
                part[(q_w * 128 + mi * 16 + lid) * 2 + hh] = 0.f;
        }
        __syncthreads();

        // ---- combine h-halves -> masked scores (key-pair per thread) ----
        {
            int q = tid >> 6, kp = tid & 63;
            float4 pv = *(const float4*)(part + (q * 128 + 2 * kp) * 2);
            float2 vm = __ldg((const float2*)(VM + b * NN + k0 + 2 * kp));
            int kg = k0 + 2 * kp, qq = qb + q;
            float cm0 = (kg     <= qq) ? vm.x : 0.f;
            float cm1 = (kg + 1 <= qq) ? vm.y : 0.f;
            float s0 = (pv.x + pv.y + b2v) * cm0;
            float s1 = (pv.z + pv.w + b2v) * cm1;
            u32 hp, lp; split2(s0, s1, hp, lp);
            u32 o = SCSWZ((u32)(q * 256 + kp * 4));
            *(u32*)(sm + OSCH + o) = hp;
            *(u32*)(sm + OSCL + o) = lp;
        }
        __syncthreads();

        // ===== encoded^T mma: ec[d, q] += X^T . scores^T (3 mma/kt) =====
        {
            const int kt_hi = min(8, ((qb + 1 - k0) >> 4) + 1);
            #pragma unroll 1
            for (int kt = 0; kt < kt_hi; kt++) {
                u32 axh[4], axl[4];
                u32 xo = xab + (u32)(kt * 2048);
                ldsm_x4t(axh, xh_b + xo);
                ldsm_x4t(axl, xl_b + xo);
                u32 so = (sb_raw + (u32)(kt * 32)) ^ sb_mask;
                u32 bsh[2], bsl[2];
                ldsm_x2(bsh, smb + OSCH + so);
                ldsm_x2(bsl, smb + OSCL + so);
                mma_bf16(ec, axh, bsh);
                mma_bf16(ec, axh, bsl);
                mma_bf16(ec, axl, bsh);
            }
        }
        __syncthreads();   // buffer free for next tile's prefetch

        if (t + 1 < nt && tid == 0) {
            mbar_expect(mbar, 32768);
            bulkcp(smb + OXH, g_xh + b * 65536 + (t + 1) * 16384, 16384, mbar);
            bulkcp(smb + OXL, g_xl + b * 65536 + (t + 1) * 16384, 16384, mbar);
        }
    }

    // ---- output: ec cols 0,1 = q0,q1; rows = d (lanes with lid%4 == 0) ----
    if ((lid & 3) == 0) {
        int r = lid >> 2;                  // 0..7
        int d0 = wid * 16 + r;
        float* o0 = OUT + (b * NN + qb) * DD;
        float* o1 = OUT + (b * NN + qb + 1) * DD;
        o0[d0]     = ec[0];
        o1[d0]     = ec[1];
        o0[d0 + 8] = ec[2];
        o1[d0 + 8] = ec[3];
    }
}

// ---------------------------------------------------------------------------
// Inputs (metadata order):
//  0 past_lengths (unused)  1 user_embeddings [8,512,64] f32  2 valid_mask [8,512]
//  3 W1 [64,256]  4 b1 [64]  5 prelu_a [1]  6 W2 [1,64]  7 b2 [1]
// Output: encoded [8,512,64] f32
// ---------------------------------------------------------------------------
extern "C" void kernel_launch(void* const* d_in, const int* in_sizes, int n_in,
                              void* d_out, int out_size)
{
    const float* X  = (const float*)d_in[1];
    const float* VM = (const float*)d_in[2];
    const float* W1 = (const float*)d_in[3];
    const float* b1 = (const float*)d_in[4];
    const float* pa = (const float*)d_in[5];
    const float* W2 = (const float*)d_in[6];
    const float* b2 = (const float*)d_in[7];
    float* OUT = (float*)d_out;

    cudaFuncSetAttribute(din_mma, cudaFuncAttributeMaxDynamicSharedMemorySize, SMEM_DYN);
    prep<<<256, 128>>>(X, W1, b1);
    din_mma<<<BB * NN / 2, 128, SMEM_DYN>>>(X, VM, W1, pa, W2, b2, OUT);
}